// round 5
// baseline (speedup 1.0000x reference)
#include <cuda_runtime.h>

// NMS peak detection, exact:
//   x: (8, 1, 1024, 1024) fp32
//   peak(p) <=> x[p] > 0.5 && no q in 51x51 window with x[q] > x[p]
//   output (float32): (4096, 4) rows [n, c, h, w] in row-major linear-index order, -1 fill.
//
// 16x16 aligned tile grid (64x64 tiles/image):
//   cand:   block == tile, one thread/element. Tile max -> g_tilemax. Elements equal to
//           tile max (> 0.5) -> deterministic per-tile slots (3, for exact tie handling).
//           A peak must equal its own tile max (16 <= R+1 = 26 -> tile inside window).
//           Also fuses output -1 fill + peak counter reset (no reset kernel).
//   verify: warp == tile. Window covers <=25 tiles. Fully-inside tile with max > pv
//           kills instantly (no element loads). Boundary offenders get exact warp scan.
//           pv == own tilemax, so no image load on the common path.
//   rank:   warp per peak, lanes stream g_peaks from L2 (no smem), O(n^2/32).

#define IMG_SH 10          // 1024
#define NIMG   8
#define RAD    25
#define TS     16
#define NT     64          // tiles per side
#define TILES_PER_IMG (NT * NT)
#define NTILES (NIMG * TILES_PER_IMG)
#define MAXD   4096
#define PEAK_CAP 8192
#define FULL   0xffffffffu

__device__ int   g_cand[NTILES * 3];   // linear indices, -1 = empty
__device__ float g_tilemax[NTILES];
__device__ int   g_peak_count;
__device__ int   g_peaks[PEAK_CAP];

// grid (64, 64, 8), block 256. One thread per element.
__global__ void cand_kernel(const float* __restrict__ x, float* __restrict__ out) {
    const int n  = blockIdx.z;
    const int ty = blockIdx.y;
    const int tx = blockIdx.x;
    const int tid  = threadIdx.x;
    const int lane = tid & 31;
    const int wid  = tid >> 5;
    const int tile = (n << 12) + (ty << 6) + tx;

    // Fused init: -1 fill of output (first 16 blocks of image 0) + counter reset.
    if (n == 0 && ty == 0) {
        if (tx < 16)
            reinterpret_cast<float4*>(out)[(tx << 8) + tid] =
                make_float4(-1.0f, -1.0f, -1.0f, -1.0f);
        if (tx == 16 && tid == 0) g_peak_count = 0;
    }

    const int h = (ty << 4) + (tid >> 4);
    const int w = (tx << 4) + (tid & 15);
    const float v = __ldg(&x[((size_t)n << 20) + (h << IMG_SH) + w]);

    __shared__ float wmax[8];
    __shared__ int   s_cnt;

    float m = v;
    #pragma unroll
    for (int off = 16; off; off >>= 1)
        m = fmaxf(m, __shfl_xor_sync(FULL, m, off));
    if (lane == 0) wmax[wid] = m;
    if (tid == 0) s_cnt = 0;
    __syncthreads();
    if (wid == 0) {
        float t = (lane < 8) ? wmax[lane] : -1.0f;
        #pragma unroll
        for (int off = 4; off; off >>= 1)
            t = fmaxf(t, __shfl_xor_sync(FULL, t, off));
        if (lane == 0) {
            wmax[0] = t;
            g_tilemax[tile] = t;
        }
    }
    // default-empty slots
    if (tid < 3) g_cand[tile * 3 + tid] = -1;
    __syncthreads();

    const float tmax = wmax[0];
    if (tmax <= 0.5f) return;

    if (v == tmax) {
        int k = atomicAdd(&s_cnt, 1);       // smem atomic; almost always one writer
        if (k < 3)
            g_cand[tile * 3 + k] = (n << 20) + (h << IMG_SH) + w;
    }
}

// One warp per tile. 4096 blocks x 256.
__global__ void verify_kernel(const float* __restrict__ x) {
    const int lane = threadIdx.x & 31;
    const int tile = (blockIdx.x << 3) + (threadIdx.x >> 5);
    if (tile >= NTILES) return;

    int slot = (lane < 3) ? __ldg(&g_cand[tile * 3 + lane]) : -1;
    const int c0 = __shfl_sync(FULL, slot, 0);
    if (c0 < 0) return;                      // tile max <= 0.5
    const int c1 = __shfl_sync(FULL, slot, 1);
    const int c2 = __shfl_sync(FULL, slot, 2);
    const float pv = __ldg(&g_tilemax[tile]);
    const int n = tile >> 12;
    const float* img = x + ((size_t)n << 20);
    const float* tm  = g_tilemax + (n << 12);

    #pragma unroll
    for (int k = 0; k < 3; ++k) {
        const int lin = (k == 0) ? c0 : (k == 1) ? c1 : c2;
        if (lin < 0) break;
        const int rem = lin & ((1 << 20) - 1);
        const int h = rem >> IMG_SH;
        const int w = rem & 1023;

        const int hlo = max(h - RAD, 0), hhi = min(h + RAD, 1023);
        const int wlo = max(w - RAD, 0), whi = min(w + RAD, 1023);
        const int tylo = hlo >> 4, tyhi = hhi >> 4;
        const int txlo = wlo >> 4, txhi = whi >> 4;
        const int ntw = txhi - txlo + 1;
        const int nt  = (tyhi - tylo + 1) * ntw;   // <= 25

        bool off = false, inside = false;
        int tty = 0, ttx = 0;
        if (lane < nt) {
            tty = tylo + lane / ntw;
            ttx = txlo + lane % ntw;
            off = __ldg(&tm[(tty << 6) + ttx]) > pv;
            inside = ((tty << 4) >= hlo) & ((tty << 4) + 15 <= hhi) &
                     ((ttx << 4) >= wlo) & ((ttx << 4) + 15 <= whi);
        }
        // Fully-inside offender -> instant kill.
        if (__any_sync(FULL, off && inside)) continue;

        unsigned bmask = __ballot_sync(FULL, off && !inside);
        bool bad = false;
        while (bmask && !bad) {
            const int b = __ffs(bmask) - 1;
            bmask &= bmask - 1;
            const int oty = tylo + b / ntw;
            const int otx = txlo + b % ntw;
            const int rlo = max(hlo, oty << 4), rhi = min(hhi, (oty << 4) + 15);
            const int clo = max(wlo, otx << 4), chi = min(whi, (otx << 4) + 15);
            const int nc  = chi - clo + 1;
            const int tot = (rhi - rlo + 1) * nc;
            for (int base = 0; base < tot; base += 32) {
                const int i = base + lane;
                bool hit = false;
                if (i < tot) {
                    const int r = rlo + i / nc;
                    const int c = clo + i % nc;
                    hit = __ldg(&img[(r << IMG_SH) + c]) > pv;
                }
                if (__any_sync(FULL, hit)) { bad = true; break; }
            }
        }
        if (!bad && lane == 0) {
            int s = atomicAdd(&g_peak_count, 1);
            if (s < PEAK_CAP) g_peaks[s] = lin;
        }
    }
}

// Warp per peak; lanes stream g_peaks straight from L2 (coalesced), no smem.
__global__ void rank_kernel(float* __restrict__ out) {
    const int cnt  = min(g_peak_count, PEAK_CAP);
    const int lane = threadIdx.x & 31;
    const int gw   = (blockIdx.x * blockDim.x + threadIdx.x) >> 5;
    const int nw   = (gridDim.x * blockDim.x) >> 5;

    for (int i = gw; i < cnt; i += nw) {
        const int lin = __ldg(&g_peaks[i]);
        int r = 0;
        for (int j = lane; j < cnt; j += 32) r += (__ldg(&g_peaks[j]) < lin);
        #pragma unroll
        for (int off = 16; off; off >>= 1)
            r += __shfl_xor_sync(FULL, r, off);
        if (lane == 0 && r < MAXD) {
            const int rem = lin & ((1 << 20) - 1);
            reinterpret_cast<float4*>(out)[r] =
                make_float4((float)(lin >> 20), 0.0f,
                            (float)(rem >> IMG_SH), (float)(rem & 1023));
        }
    }
}

extern "C" void kernel_launch(void* const* d_in, const int* in_sizes, int n_in,
                              void* d_out, int out_size) {
    const float* x = (const float*)d_in[0];
    float* out = (float*)d_out;

    dim3 grid(NT, NT, NIMG);
    cand_kernel<<<grid, 256>>>(x, out);

    verify_kernel<<<NTILES / 8, 256>>>(x);

    rank_kernel<<<256, 256>>>(out);
}

// round 8
// speedup vs baseline: 1.5029x; 1.5029x over previous
#include <cuda_runtime.h>

// NMS peak detection, exact:
//   x: (8, 1, 1024, 1024) fp32
//   peak(p) <=> x[p] > 0.5 && no q in 51x51 window with x[q] > x[p]
//   output (float32): (4096, 4) rows [n, c, h, w] in row-major linear-index order, -1 fill.
//
// 16x16 aligned tile grid (64x64 tiles/image):
//   cand:   WARP == tile. Lane loads 8 elems (two float4), 7 reg fmax + one 5-step
//           shuffle reduce per 256 elems. Tile max -> g_tilemax; elements equal to the
//           tile max (> 0.5) -> 3 per-tile slots (exact tie handling). A peak must equal
//           its own tile max (16 <= R+1 = 26). Fuses output -1 fill + counter reset.
//   verify: warp == tile. Window covers <=25 tiles. Fully-inside tile with max > pv
//           kills with zero element loads; boundary offenders get exact warp scan.
//   rank:   warp per peak, lanes stream g_peaks from L2, O(n^2/32) -> nonzero() order.

#define IMG_SH 10          // 1024
#define NIMG   8
#define RAD    25
#define NT     64          // tiles per side
#define NTILES (NIMG * NT * NT)
#define MAXD   4096
#define PEAK_CAP 8192
#define FULL   0xffffffffu

__device__ int   g_cand[NTILES * 3];   // linear indices, -1 = empty
__device__ float g_tilemax[NTILES];
__device__ int   g_peak_count;
__device__ int   g_peaks[PEAK_CAP];

// 1024 blocks x 256 threads; 8 warps/block, warp == one 16x16 tile.
__global__ void cand_kernel(const float* __restrict__ x, float* __restrict__ out) {
    const int tid  = threadIdx.x;
    const int lane = tid & 31;
    const int wid  = tid >> 5;
    const int tile = (blockIdx.x << 3) + wid;

    // Fused init: -1 fill of 4096x4 output (blocks 0..15) + counter reset (block 16).
    if (blockIdx.x < 16)
        reinterpret_cast<float4*>(out)[(blockIdx.x << 8) + tid] =
            make_float4(-1.0f, -1.0f, -1.0f, -1.0f);
    if (blockIdx.x == 16 && tid == 0) g_peak_count = 0;

    const int n  = tile >> 12;
    const int ty = (tile >> 6) & 63;
    const int tx = tile & 63;
    const int h  = (ty << 4) + (lane >> 1);
    const int w0 = (tx << 4) + ((lane & 1) << 3);
    const float* p = x + ((size_t)n << 20) + (h << IMG_SH) + w0;

    const float4 a = *reinterpret_cast<const float4*>(p);
    const float4 b = *reinterpret_cast<const float4*>(p + 4);

    float m = fmaxf(fmaxf(fmaxf(a.x, a.y), fmaxf(a.z, a.w)),
                    fmaxf(fmaxf(b.x, b.y), fmaxf(b.z, b.w)));
    #pragma unroll
    for (int off = 16; off; off >>= 1)
        m = fmaxf(m, __shfl_xor_sync(FULL, m, off));
    // m == tile max on every lane now.

    if (lane == 0) g_tilemax[tile] = m;
    if (lane < 3)  g_cand[tile * 3 + lane] = -1;

    if (m <= 0.5f) return;

    __shared__ int scnt[8];
    if (lane == 0) scnt[wid] = 0;
    __syncwarp();

    const float v[8] = {a.x, a.y, a.z, a.w, b.x, b.y, b.z, b.w};
    const int base = (n << 20) + (h << IMG_SH) + w0;
    #pragma unroll
    for (int k = 0; k < 8; ++k) {
        if (v[k] == m) {
            int s = atomicAdd(&scnt[wid], 1);
            if (s < 3) g_cand[tile * 3 + s] = base + k;
        }
    }
}

// One warp per tile. Tilemax pruning; exact scan only on boundary offenders.
__global__ void verify_kernel(const float* __restrict__ x) {
    const int lane = threadIdx.x & 31;
    const int tile = (blockIdx.x << 3) + (threadIdx.x >> 5);

    int slot = (lane < 3) ? __ldg(&g_cand[tile * 3 + lane]) : -1;
    const int c0 = __shfl_sync(FULL, slot, 0);
    if (c0 < 0) return;                      // tile max <= 0.5
    const int c1 = __shfl_sync(FULL, slot, 1);
    const int c2 = __shfl_sync(FULL, slot, 2);
    const float pv = __ldg(&g_tilemax[tile]);
    const int n = tile >> 12;
    const float* img = x + ((size_t)n << 20);
    const float* tm  = g_tilemax + (n << 12);

    #pragma unroll
    for (int k = 0; k < 3; ++k) {
        const int lin = (k == 0) ? c0 : (k == 1) ? c1 : c2;
        if (lin < 0) break;
        const int rem = lin & ((1 << 20) - 1);
        const int h = rem >> IMG_SH;
        const int w = rem & 1023;

        const int hlo = max(h - RAD, 0), hhi = min(h + RAD, 1023);
        const int wlo = max(w - RAD, 0), whi = min(w + RAD, 1023);
        const int tylo = hlo >> 4, tyhi = hhi >> 4;
        const int txlo = wlo >> 4, txhi = whi >> 4;
        const int ntw = txhi - txlo + 1;
        const int nt  = (tyhi - tylo + 1) * ntw;   // <= 25

        bool off = false, inside = false;
        if (lane < nt) {
            const int tty = tylo + lane / ntw;
            const int ttx = txlo + lane % ntw;
            off = __ldg(&tm[(tty << 6) + ttx]) > pv;
            inside = ((tty << 4) >= hlo) & ((tty << 4) + 15 <= hhi) &
                     ((ttx << 4) >= wlo) & ((ttx << 4) + 15 <= whi);
        }
        if (__any_sync(FULL, off && inside)) continue;   // instant kill

        unsigned bmask = __ballot_sync(FULL, off && !inside);
        bool bad = false;
        while (bmask && !bad) {
            const int b = __ffs(bmask) - 1;
            bmask &= bmask - 1;
            const int oty = tylo + b / ntw;
            const int otx = txlo + b % ntw;
            const int rlo = max(hlo, oty << 4), rhi = min(hhi, (oty << 4) + 15);
            const int clo = max(wlo, otx << 4), chi = min(whi, (otx << 4) + 15);
            const int nc  = chi - clo + 1;
            const int tot = (rhi - rlo + 1) * nc;
            for (int bse = 0; bse < tot; bse += 32) {
                const int i = bse + lane;
                bool hit = false;
                if (i < tot) {
                    const int r = rlo + i / nc;
                    const int c = clo + i % nc;
                    hit = __ldg(&img[(r << IMG_SH) + c]) > pv;
                }
                if (__any_sync(FULL, hit)) { bad = true; break; }
            }
        }
        if (!bad && lane == 0) {
            int s = atomicAdd(&g_peak_count, 1);
            if (s < PEAK_CAP) g_peaks[s] = lin;
        }
    }
}

// Warp per peak; lanes stream g_peaks from L2 (coalesced), shuffle-reduce rank.
__global__ void rank_kernel(float* __restrict__ out) {
    const int cnt  = min(g_peak_count, PEAK_CAP);
    const int lane = threadIdx.x & 31;
    const int gw   = (blockIdx.x * blockDim.x + threadIdx.x) >> 5;
    const int nw   = (gridDim.x * blockDim.x) >> 5;

    for (int i = gw; i < cnt; i += nw) {
        const int lin = __ldg(&g_peaks[i]);
        int r = 0;
        for (int j = lane; j < cnt; j += 32) r += (__ldg(&g_peaks[j]) < lin);
        #pragma unroll
        for (int off = 16; off; off >>= 1)
            r += __shfl_xor_sync(FULL, r, off);
        if (lane == 0 && r < MAXD) {
            const int rem = lin & ((1 << 20) - 1);
            reinterpret_cast<float4*>(out)[r] =
                make_float4((float)(lin >> 20), 0.0f,
                            (float)(rem >> IMG_SH), (float)(rem & 1023));
        }
    }
}

extern "C" void kernel_launch(void* const* d_in, const int* in_sizes, int n_in,
                              void* d_out, int out_size) {
    const float* x = (const float*)d_in[0];
    float* out = (float*)d_out;

    cand_kernel<<<NTILES / 8, 256>>>(x, out);   // 1024 blocks, warp per tile

    verify_kernel<<<NTILES / 8, 256>>>(x);

    rank_kernel<<<256, 256>>>(out);
}

// round 9
// speedup vs baseline: 1.6465x; 1.0955x over previous
#include <cuda_runtime.h>

// NMS peak detection, exact:
//   x: (8, 1, 1024, 1024) fp32
//   peak(p) <=> x[p] > 0.5 && no q in 51x51 window with x[q] > x[p]
//   output (float32): (4096, 4) rows [n, c, h, w] in row-major linear-index order, -1 fill.
//
// 16x16 aligned tile grid (64x64 tiles/image):
//   cand:   warp == horizontally adjacent TILE PAIR (32 floats wide = one 128B line/row).
//           Lane (row=lane>>3 (+4k), col=(lane&7)*4): each LDG.128 covers 4 full lines.
//           lane bit2 selects the tile; shfl offsets {16,8,2,1} reduce each 16-lane tile
//           group. Tile max -> g_tilemax; elems == tile max (> 0.5) -> 3 per-tile slots.
//           Fuses output -1 fill + peak counter reset.
//   verify: warp == tile, <=25 covering tiles probed via fixed 5x5 map (const divisors).
//           Fully-inside tile with max > pv kills with zero element loads; boundary
//           offenders get exact scan with 16-wide padded row mapping (shift/mask only).
//   rank:   warp per peak, lanes stream g_peaks from L2, O(n^2/32) -> nonzero() order.

#define IMG_SH 10          // 1024
#define NIMG   8
#define RAD    25
#define NT     64          // tiles per side
#define NTILES (NIMG * NT * NT)
#define MAXD   4096
#define PEAK_CAP 8192
#define FULL   0xffffffffu

__device__ int   g_cand[NTILES * 3];   // linear indices, -1 = empty
__device__ float g_tilemax[NTILES];
__device__ int   g_peak_count;
__device__ int   g_peaks[PEAK_CAP];

// 2048 blocks x 256 threads; 8 warps/block, warp == one 2-tile pair (16 tiles/block).
__global__ void cand_kernel(const float* __restrict__ x, float* __restrict__ out) {
    const int tid  = threadIdx.x;
    const int lane = tid & 31;
    const int wid  = tid >> 5;

    // Fused init: -1 fill of 4096x4 output (blocks 0..15) + counter reset (block 16).
    if (blockIdx.x < 16)
        reinterpret_cast<float4*>(out)[(blockIdx.x << 8) + tid] =
            make_float4(-1.0f, -1.0f, -1.0f, -1.0f);
    if (blockIdx.x == 16 && tid == 0) g_peak_count = 0;

    const int tp    = (blockIdx.x << 3) + wid;   // tile-pair id
    const int tileA = tp << 1;
    const int n     = tileA >> 12;
    const int ty    = (tileA >> 6) & 63;
    const int txA   = tileA & 63;                // even
    const int row0  = lane >> 3;                 // 0..3
    const int colp  = (lane & 7) << 2;           // 0..28 within 32-wide pair

    const float* base = x + ((size_t)n << 20)
                          + (((ty << 4) + row0) << IMG_SH)
                          + (txA << 4) + colp;

    float4 f0 = *reinterpret_cast<const float4*>(base);
    float4 f1 = *reinterpret_cast<const float4*>(base + (4 << IMG_SH));
    float4 f2 = *reinterpret_cast<const float4*>(base + (8 << IMG_SH));
    float4 f3 = *reinterpret_cast<const float4*>(base + (12 << IMG_SH));

    float m = fmaxf(fmaxf(fmaxf(f0.x, f0.y), fmaxf(f0.z, f0.w)),
              fmaxf(fmaxf(fmaxf(f1.x, f1.y), fmaxf(f1.z, f1.w)),
              fmaxf(fmaxf(fmaxf(f2.x, f2.y), fmaxf(f2.z, f2.w)),
                    fmaxf(fmaxf(f3.x, f3.y), fmaxf(f3.z, f3.w)))));
    // Reduce over the 16 lanes sharing bit2 (= same tile): offsets keep bit2 fixed.
    m = fmaxf(m, __shfl_xor_sync(FULL, m, 16));
    m = fmaxf(m, __shfl_xor_sync(FULL, m, 8));
    m = fmaxf(m, __shfl_xor_sync(FULL, m, 2));
    m = fmaxf(m, __shfl_xor_sync(FULL, m, 1));

    const int myTile = tileA + ((lane >> 2) & 1);
    if (lane == 0 || lane == 4) g_tilemax[myTile] = m;
    if (lane < 3)               g_cand[tileA * 3 + lane] = -1;
    if (lane >= 4 && lane < 7)  g_cand[(tileA + 1) * 3 + (lane - 4)] = -1;

    __shared__ int scnt[16];
    if (lane == 0 || lane == 4) scnt[(wid << 1) | (lane >> 2)] = 0;
    __syncwarp();

    if (m <= 0.5f) return;

    const int sidx = (wid << 1) | ((lane >> 2) & 1);
    const int lin0 = (n << 20) + (((ty << 4) + row0) << IMG_SH) + (txA << 4) + colp;
    const float v[16] = {f0.x, f0.y, f0.z, f0.w, f1.x, f1.y, f1.z, f1.w,
                         f2.x, f2.y, f2.z, f2.w, f3.x, f3.y, f3.z, f3.w};
    #pragma unroll
    for (int k = 0; k < 16; ++k) {
        if (v[k] == m) {
            int s = atomicAdd(&scnt[sidx], 1);
            if (s < 3) g_cand[myTile * 3 + s] = lin0 + ((k >> 2) << (IMG_SH + 2)) + (k & 3);
        }
    }
}

// One warp per tile. Tilemax pruning; exact scan only on boundary offenders.
// All index math uses constant divisors (5 for the probe grid, 16 for row scan).
__global__ void verify_kernel(const float* __restrict__ x) {
    const int lane = threadIdx.x & 31;
    const int tile = (blockIdx.x << 3) + (threadIdx.x >> 5);

    int slot = (lane < 3) ? __ldg(&g_cand[tile * 3 + lane]) : -1;
    const int c0 = __shfl_sync(FULL, slot, 0);
    if (c0 < 0) return;                      // tile max <= 0.5
    const int c1 = __shfl_sync(FULL, slot, 1);
    const int c2 = __shfl_sync(FULL, slot, 2);
    const float pv = __ldg(&g_tilemax[tile]);
    const int n = tile >> 12;
    const float* img = x + ((size_t)n << 20);
    const float* tm  = g_tilemax + (n << 12);

    #pragma unroll
    for (int k = 0; k < 3; ++k) {
        const int lin = (k == 0) ? c0 : (k == 1) ? c1 : c2;
        if (lin < 0) break;
        const int rem = lin & ((1 << 20) - 1);
        const int h = rem >> IMG_SH;
        const int w = rem & 1023;

        const int hlo = max(h - RAD, 0), hhi = min(h + RAD, 1023);
        const int wlo = max(w - RAD, 0), whi = min(w + RAD, 1023);
        const int tylo = hlo >> 4, tyhi = hhi >> 4;
        const int txlo = wlo >> 4, txhi = whi >> 4;

        // Fixed 5x5 probe grid; constant divisor -> mul/shift. Guarded by range.
        const int dy = lane / 5, dx = lane - dy * 5;   // const div
        const int tty = tylo + dy, ttx = txlo + dx;
        bool off = false, inside = false;
        if (lane < 25 && tty <= tyhi && ttx <= txhi) {
            off = __ldg(&tm[(tty << 6) + ttx]) > pv;
            inside = ((tty << 4) >= hlo) & ((tty << 4) + 15 <= hhi) &
                     ((ttx << 4) >= wlo) & ((ttx << 4) + 15 <= whi);
        }
        if (__any_sync(FULL, off && inside)) continue;   // instant kill

        unsigned bmask = __ballot_sync(FULL, off && !inside);
        bool bad = false;
        while (bmask && !bad) {
            const int b = __ffs(bmask) - 1;
            bmask &= bmask - 1;
            const int by = b / 5;                        // const div
            const int oty = tylo + by, otx = txlo + (b - by * 5);
            const int rlo = max(hlo, oty << 4), rhi = min(hhi, (oty << 4) + 15);
            const int clo = max(wlo, otx << 4), chi = min(whi, (otx << 4) + 15);
            const int ncm1 = chi - clo;                  // 0..15
            const int tot  = (rhi - rlo + 1) << 4;       // padded 16-wide rows
            for (int bse = 0; bse < tot; bse += 32) {
                const int i = bse + lane;
                bool hit = false;
                if (i < tot && (i & 15) <= ncm1) {
                    const int r = rlo + (i >> 4);
                    const int c = clo + (i & 15);
                    hit = __ldg(&img[(r << IMG_SH) + c]) > pv;
                }
                if (__any_sync(FULL, hit)) { bad = true; break; }
            }
        }
        if (!bad && lane == 0) {
            int s = atomicAdd(&g_peak_count, 1);
            if (s < PEAK_CAP) g_peaks[s] = lin;
        }
    }
}

// Warp per peak; lanes stream g_peaks from L2 (coalesced), shuffle-reduce rank.
__global__ void rank_kernel(float* __restrict__ out) {
    const int cnt  = min(g_peak_count, PEAK_CAP);
    const int lane = threadIdx.x & 31;
    const int gw   = (blockIdx.x * blockDim.x + threadIdx.x) >> 5;
    const int nw   = (gridDim.x * blockDim.x) >> 5;

    for (int i = gw; i < cnt; i += nw) {
        const int lin = __ldg(&g_peaks[i]);
        int r = 0;
        for (int j = lane; j < cnt; j += 32) r += (__ldg(&g_peaks[j]) < lin);
        #pragma unroll
        for (int off = 16; off; off >>= 1)
            r += __shfl_xor_sync(FULL, r, off);
        if (lane == 0 && r < MAXD) {
            const int rem = lin & ((1 << 20) - 1);
            reinterpret_cast<float4*>(out)[r] =
                make_float4((float)(lin >> 20), 0.0f,
                            (float)(rem >> IMG_SH), (float)(rem & 1023));
        }
    }
}

extern "C" void kernel_launch(void* const* d_in, const int* in_sizes, int n_in,
                              void* d_out, int out_size) {
    const float* x = (const float*)d_in[0];
    float* out = (float*)d_out;

    cand_kernel<<<NTILES / 16, 256>>>(x, out);   // 2048 blocks, warp per tile pair

    verify_kernel<<<NTILES / 8, 256>>>(x);

    rank_kernel<<<256, 256>>>(out);
}

// round 10
// speedup vs baseline: 1.7391x; 1.0563x over previous
#include <cuda_runtime.h>

// NMS peak detection, exact:
//   x: (8, 1, 1024, 1024) fp32
//   peak(p) <=> x[p] > 0.5 && no q in 51x51 window with x[q] > x[p]
//   output (float32): (4096, 4) rows [n, c, h, w] in row-major linear-index order, -1 fill.
//
// 16x16 aligned tile grid (64x64 tiles/image):
//   cand:   warp == 2x2 TILE QUAD (32x32 pixels). Lane: row=lane>>3 (+4j), col=(lane&7)*4.
//           8 float4 loads/lane (MLP=8, all full 128B lines). Two shuffle chains
//           ({16,8,2,1}, lane-bit2 = left/right tile) give the 4 tile maxes.
//           Tile max -> g_tilemax; elems == tile max (> 0.5) -> 3 per-tile slots.
//           Fuses output -1 fill + peak counter reset.
//   verify: warp == tile, <=25 covering tiles probed via fixed 5x5 map (const divisors).
//           Fully-inside tile with max > pv kills with zero element loads; boundary
//           offenders get exact scan with 16-wide padded row mapping (shift/mask only).
//   rank:   warp per peak; peaks staged in SMEM per block (stride-32 LDS inner loop).

#define IMG_SH 10          // 1024
#define NIMG   8
#define RAD    25
#define NT     64          // tiles per side
#define NTILES (NIMG * NT * NT)
#define MAXD   4096
#define PEAK_CAP 8192
#define FULL   0xffffffffu

__device__ int   g_cand[NTILES * 3];   // linear indices, -1 = empty
__device__ float g_tilemax[NTILES];
__device__ int   g_peak_count;
__device__ int   g_peaks[PEAK_CAP];

// 1024 blocks x 256 threads; 8 warps/block, warp == one 2x2 tile quad.
__global__ void cand_kernel(const float* __restrict__ x, float* __restrict__ out) {
    const int tid  = threadIdx.x;
    const int lane = tid & 31;
    const int wid  = tid >> 5;

    // Fused init: -1 fill of 4096x4 output (blocks 0..15) + counter reset (block 16).
    if (blockIdx.x < 16)
        reinterpret_cast<float4*>(out)[(blockIdx.x << 8) + tid] =
            make_float4(-1.0f, -1.0f, -1.0f, -1.0f);
    if (blockIdx.x == 16 && tid == 0) g_peak_count = 0;

    const int quad = (blockIdx.x << 3) + wid;    // 0..8191
    const int n    = quad >> 10;
    const int qy   = (quad >> 5) & 31;
    const int qx   = quad & 31;
    const int row0 = lane >> 3;                  // 0..3
    const int col  = (lane & 7) << 2;            // 0..28 within 32-wide quad

    const float* base = x + ((size_t)n << 20)
                          + (((qy << 5) + row0) << IMG_SH)
                          + (qx << 5) + col;

    float4 f[8];
    #pragma unroll
    for (int j = 0; j < 8; ++j)
        f[j] = *reinterpret_cast<const float4*>(base + ((j << 2) << IMG_SH));

    float mTop = -1.0f, mBot = -1.0f;
    #pragma unroll
    for (int j = 0; j < 4; ++j)
        mTop = fmaxf(mTop, fmaxf(fmaxf(f[j].x, f[j].y), fmaxf(f[j].z, f[j].w)));
    #pragma unroll
    for (int j = 4; j < 8; ++j)
        mBot = fmaxf(mBot, fmaxf(fmaxf(f[j].x, f[j].y), fmaxf(f[j].z, f[j].w)));

    // Reduce over the 16 lanes sharing bit2 (= same left/right tile column).
    #pragma unroll
    for (int k = 0; k < 4; ++k) {
        const int off = (int[]){16, 8, 2, 1}[k];
        mTop = fmaxf(mTop, __shfl_xor_sync(FULL, mTop, off));
        mBot = fmaxf(mBot, __shfl_xor_sync(FULL, mBot, off));
    }

    const int myTx    = (qx << 1) + ((lane >> 2) & 1);
    const int tileTop = (n << 12) | ((qy << 1) << 6) | myTx;
    const int tileBot = tileTop + 64;
    if (lane == 0 || lane == 4) {
        g_tilemax[tileTop] = mTop;
        g_tilemax[tileBot] = mBot;
    }
    // Init the quad's 12 candidate slots (4 tiles x 3).
    if (lane < 12) {
        const int t = lane / 3;                  // const div: 0..3 = TL,TR,BL,BR
        const int tileI = (n << 12) | (((qy << 1) + (t >> 1)) << 6) | ((qx << 1) + (t & 1));
        g_cand[tileI * 3 + (lane - t * 3)] = -1;
    }

    __shared__ int scnt[32];
    if (lane < 4) scnt[(wid << 2) + lane] = 0;
    __syncwarp();

    if (fmaxf(mTop, mBot) <= 0.5f) return;

    const int lin0 = (n << 20) + (((qy << 5) + row0) << IMG_SH) + (qx << 5) + col;
    #pragma unroll
    for (int j = 0; j < 8; ++j) {
        const float m = (j < 4) ? mTop : mBot;
        const float vv[4] = {f[j].x, f[j].y, f[j].z, f[j].w};
        #pragma unroll
        for (int c = 0; c < 4; ++c) {
            if (vv[c] == m) {
                const int tsel = ((j >= 4) ? 2 : 0) | ((lane >> 2) & 1);
                int s = atomicAdd(&scnt[(wid << 2) + tsel], 1);
                if (s < 3) {
                    const int tileI = (j < 4) ? tileTop : tileBot;
                    g_cand[tileI * 3 + s] = lin0 + ((j << 2) << IMG_SH) + c;
                }
            }
        }
    }
}

// One warp per tile. Tilemax pruning; exact scan only on boundary offenders.
__global__ void verify_kernel(const float* __restrict__ x) {
    const int lane = threadIdx.x & 31;
    const int tile = (blockIdx.x << 3) + (threadIdx.x >> 5);

    int slot = (lane < 3) ? __ldg(&g_cand[tile * 3 + lane]) : -1;
    const int c0 = __shfl_sync(FULL, slot, 0);
    if (c0 < 0) return;                      // tile max <= 0.5
    const int c1 = __shfl_sync(FULL, slot, 1);
    const int c2 = __shfl_sync(FULL, slot, 2);
    const float pv = __ldg(&g_tilemax[tile]);
    const int n = tile >> 12;
    const float* img = x + ((size_t)n << 20);
    const float* tm  = g_tilemax + (n << 12);

    #pragma unroll
    for (int k = 0; k < 3; ++k) {
        const int lin = (k == 0) ? c0 : (k == 1) ? c1 : c2;
        if (lin < 0) break;
        const int rem = lin & ((1 << 20) - 1);
        const int h = rem >> IMG_SH;
        const int w = rem & 1023;

        const int hlo = max(h - RAD, 0), hhi = min(h + RAD, 1023);
        const int wlo = max(w - RAD, 0), whi = min(w + RAD, 1023);
        const int tylo = hlo >> 4, tyhi = hhi >> 4;
        const int txlo = wlo >> 4, txhi = whi >> 4;

        // Fixed 5x5 probe grid; constant divisor -> mul/shift. Guarded by range.
        const int dy = lane / 5, dx = lane - dy * 5;
        const int tty = tylo + dy, ttx = txlo + dx;
        bool off = false, inside = false;
        if (lane < 25 && tty <= tyhi && ttx <= txhi) {
            off = __ldg(&tm[(tty << 6) + ttx]) > pv;
            inside = ((tty << 4) >= hlo) & ((tty << 4) + 15 <= hhi) &
                     ((ttx << 4) >= wlo) & ((ttx << 4) + 15 <= whi);
        }
        if (__any_sync(FULL, off && inside)) continue;   // instant kill

        unsigned bmask = __ballot_sync(FULL, off && !inside);
        bool bad = false;
        while (bmask && !bad) {
            const int b = __ffs(bmask) - 1;
            bmask &= bmask - 1;
            const int by = b / 5;
            const int oty = tylo + by, otx = txlo + (b - by * 5);
            const int rlo = max(hlo, oty << 4), rhi = min(hhi, (oty << 4) + 15);
            const int clo = max(wlo, otx << 4), chi = min(whi, (otx << 4) + 15);
            const int ncm1 = chi - clo;                  // 0..15
            const int tot  = (rhi - rlo + 1) << 4;       // padded 16-wide rows
            for (int bse = 0; bse < tot; bse += 32) {
                const int i = bse + lane;
                bool hit = false;
                if (i < tot && (i & 15) <= ncm1) {
                    const int r = rlo + (i >> 4);
                    const int c = clo + (i & 15);
                    hit = __ldg(&img[(r << IMG_SH) + c]) > pv;
                }
                if (__any_sync(FULL, hit)) { bad = true; break; }
            }
        }
        if (!bad && lane == 0) {
            int s = atomicAdd(&g_peak_count, 1);
            if (s < PEAK_CAP) g_peaks[s] = lin;
        }
    }
}

// Warp per peak; peaks staged in SMEM (stride-32 LDS inner loop, conflict-free).
__global__ void rank_kernel(float* __restrict__ out) {
    __shared__ int sp[PEAK_CAP];
    const int cnt  = min(g_peak_count, PEAK_CAP);
    for (int j = threadIdx.x; j < cnt; j += blockDim.x) sp[j] = g_peaks[j];
    __syncthreads();

    const int lane = threadIdx.x & 31;
    const int gw   = (blockIdx.x * blockDim.x + threadIdx.x) >> 5;
    const int nw   = (gridDim.x * blockDim.x) >> 5;

    for (int i = gw; i < cnt; i += nw) {
        const int lin = sp[i];
        int r = 0;
        for (int j = lane; j < cnt; j += 32) r += (sp[j] < lin);
        #pragma unroll
        for (int off = 16; off; off >>= 1)
            r += __shfl_xor_sync(FULL, r, off);
        if (lane == 0 && r < MAXD) {
            const int rem = lin & ((1 << 20) - 1);
            reinterpret_cast<float4*>(out)[r] =
                make_float4((float)(lin >> 20), 0.0f,
                            (float)(rem >> IMG_SH), (float)(rem & 1023));
        }
    }
}

extern "C" void kernel_launch(void* const* d_in, const int* in_sizes, int n_in,
                              void* d_out, int out_size) {
    const float* x = (const float*)d_in[0];
    float* out = (float*)d_out;

    cand_kernel<<<1024, 256>>>(x, out);      // warp per 2x2 tile quad

    verify_kernel<<<NTILES / 8, 256>>>(x);

    rank_kernel<<<128, 256>>>(out);
}

// round 11
// speedup vs baseline: 2.0146x; 1.1584x over previous
#include <cuda_runtime.h>

// NMS peak detection, exact:
//   x: (8, 1, 1024, 1024) fp32
//   peak(p) <=> x[p] > 0.5 && no q in 51x51 window with x[q] > x[p]
//   output (float32): (4096, 4) rows [n, c, h, w] in row-major linear-index order, -1 fill.
//
// 16x16 aligned tile grid (64x64 tiles/image):
//   cand:   warp == 2x2 TILE QUAD (32x32 pixels). 8 float4 loads/lane (full 128B lines).
//           Shuffle chains {16,8,2,1} (lane-bit2 = left/right tile) give the 4 tile maxes.
//           Emission: only lanes whose per-lane partial max equals the tile max rescan
//           their 16 registers (1-2 lanes/warp). Fuses output -1 fill + counter reset.
//   verify: warp == tile, <=25 covering tiles probed via fixed 5x5 map. Fully-inside
//           offender kills with zero element loads; boundary offenders get ONE parallel
//           8-load round per lane over the padded intersection (MLP=8, single ballot).
//   rank:   warp per peak; peaks staged in SMEM per block (stride-32 LDS inner loop).

#define IMG_SH 10          // 1024
#define NIMG   8
#define RAD    25
#define NT     64          // tiles per side
#define NTILES (NIMG * NT * NT)
#define MAXD   4096
#define PEAK_CAP 8192
#define FULL   0xffffffffu

__device__ int   g_cand[NTILES * 3];   // linear indices, -1 = empty
__device__ float g_tilemax[NTILES];
__device__ int   g_peak_count;
__device__ int   g_peaks[PEAK_CAP];

// 1024 blocks x 256 threads; 8 warps/block, warp == one 2x2 tile quad.
__global__ void cand_kernel(const float* __restrict__ x, float* __restrict__ out) {
    const int tid  = threadIdx.x;
    const int lane = tid & 31;
    const int wid  = tid >> 5;

    // Fused init: -1 fill of 4096x4 output (blocks 0..15) + counter reset (block 16).
    if (blockIdx.x < 16)
        reinterpret_cast<float4*>(out)[(blockIdx.x << 8) + tid] =
            make_float4(-1.0f, -1.0f, -1.0f, -1.0f);
    if (blockIdx.x == 16 && tid == 0) g_peak_count = 0;

    const int quad = (blockIdx.x << 3) + wid;    // 0..8191
    const int n    = quad >> 10;
    const int qy   = (quad >> 5) & 31;
    const int qx   = quad & 31;
    const int row0 = lane >> 3;                  // 0..3
    const int col  = (lane & 7) << 2;            // 0..28 within 32-wide quad

    const float* base = x + ((size_t)n << 20)
                          + (((qy << 5) + row0) << IMG_SH)
                          + (qx << 5) + col;

    float4 f[8];
    #pragma unroll
    for (int j = 0; j < 8; ++j)
        f[j] = *reinterpret_cast<const float4*>(base + ((j << 2) << IMG_SH));

    float pTop = -1.0f, pBot = -1.0f;            // per-lane partial maxes
    #pragma unroll
    for (int j = 0; j < 4; ++j)
        pTop = fmaxf(pTop, fmaxf(fmaxf(f[j].x, f[j].y), fmaxf(f[j].z, f[j].w)));
    #pragma unroll
    for (int j = 4; j < 8; ++j)
        pBot = fmaxf(pBot, fmaxf(fmaxf(f[j].x, f[j].y), fmaxf(f[j].z, f[j].w)));

    // Reduce over the 16 lanes sharing bit2 (= same left/right tile column).
    float mTop = pTop, mBot = pBot;
    mTop = fmaxf(mTop, __shfl_xor_sync(FULL, mTop, 16));
    mBot = fmaxf(mBot, __shfl_xor_sync(FULL, mBot, 16));
    mTop = fmaxf(mTop, __shfl_xor_sync(FULL, mTop, 8));
    mBot = fmaxf(mBot, __shfl_xor_sync(FULL, mBot, 8));
    mTop = fmaxf(mTop, __shfl_xor_sync(FULL, mTop, 2));
    mBot = fmaxf(mBot, __shfl_xor_sync(FULL, mBot, 2));
    mTop = fmaxf(mTop, __shfl_xor_sync(FULL, mTop, 1));
    mBot = fmaxf(mBot, __shfl_xor_sync(FULL, mBot, 1));

    const int myTx    = (qx << 1) + ((lane >> 2) & 1);
    const int tileTop = (n << 12) | ((qy << 1) << 6) | myTx;
    const int tileBot = tileTop + 64;
    if ((lane & 7) == 0 && row0 == 0) { /* lanes 0 and 4 (bit2 split) */ }
    if (lane == 0 || lane == 4) {
        g_tilemax[tileTop] = mTop;
        g_tilemax[tileBot] = mBot;
    }
    // Init the quad's 12 candidate slots (4 tiles x 3).
    if (lane < 12) {
        const int t = lane / 3;                  // const div: 0..3 = TL,TR,BL,BR
        const int tileI = (n << 12) | (((qy << 1) + (t >> 1)) << 6) | ((qx << 1) + (t & 1));
        g_cand[tileI * 3 + (lane - t * 3)] = -1;
    }

    __shared__ int scnt[32];
    if (lane < 4) scnt[(wid << 2) + lane] = 0;
    __syncwarp();

    if (fmaxf(mTop, mBot) <= 0.5f) return;

    const int lin0 = (n << 20) + (((qy << 5) + row0) << IMG_SH) + (qx << 5) + col;
    const int tsel = (wid << 2) | ((lane >> 2) & 1);

    // Only lanes holding the tile max rescan their registers (1-2 lanes per warp).
    if (pTop == mTop) {
        #pragma unroll
        for (int j = 0; j < 4; ++j) {
            const float vv[4] = {f[j].x, f[j].y, f[j].z, f[j].w};
            #pragma unroll
            for (int c = 0; c < 4; ++c)
                if (vv[c] == mTop) {
                    int s = atomicAdd(&scnt[tsel], 1);
                    if (s < 3) g_cand[tileTop * 3 + s] = lin0 + ((j << 2) << IMG_SH) + c;
                }
        }
    }
    if (pBot == mBot) {
        #pragma unroll
        for (int j = 4; j < 8; ++j) {
            const float vv[4] = {f[j].x, f[j].y, f[j].z, f[j].w};
            #pragma unroll
            for (int c = 0; c < 4; ++c)
                if (vv[c] == mBot) {
                    int s = atomicAdd(&scnt[tsel | 2], 1);
                    if (s < 3) g_cand[tileBot * 3 + s] = lin0 + ((j << 2) << IMG_SH) + c;
                }
        }
    }
}

// One warp per tile. Tilemax pruning; boundary offenders: one parallel 8-load round.
__global__ void verify_kernel(const float* __restrict__ x) {
    const int lane = threadIdx.x & 31;
    const int tile = (blockIdx.x << 3) + (threadIdx.x >> 5);

    int slot = (lane < 3) ? __ldg(&g_cand[tile * 3 + lane]) : -1;
    const int c0 = __shfl_sync(FULL, slot, 0);
    if (c0 < 0) return;                      // tile max <= 0.5
    const int c1 = __shfl_sync(FULL, slot, 1);
    const int c2 = __shfl_sync(FULL, slot, 2);
    const float pv = __ldg(&g_tilemax[tile]);
    const int n = tile >> 12;
    const float* img = x + ((size_t)n << 20);
    const float* tm  = g_tilemax + (n << 12);

    #pragma unroll
    for (int k = 0; k < 3; ++k) {
        const int lin = (k == 0) ? c0 : (k == 1) ? c1 : c2;
        if (lin < 0) break;
        const int rem = lin & ((1 << 20) - 1);
        const int h = rem >> IMG_SH;
        const int w = rem & 1023;

        const int hlo = max(h - RAD, 0), hhi = min(h + RAD, 1023);
        const int wlo = max(w - RAD, 0), whi = min(w + RAD, 1023);
        const int tylo = hlo >> 4, tyhi = hhi >> 4;
        const int txlo = wlo >> 4, txhi = whi >> 4;

        // Fixed 5x5 probe grid; constant divisor -> mul/shift. Guarded by range.
        const int dy = lane / 5, dx = lane - dy * 5;
        const int tty = tylo + dy, ttx = txlo + dx;
        bool off = false, inside = false;
        if (lane < 25 && tty <= tyhi && ttx <= txhi) {
            off = __ldg(&tm[(tty << 6) + ttx]) > pv;
            inside = ((tty << 4) >= hlo) & ((tty << 4) + 15 <= hhi) &
                     ((ttx << 4) >= wlo) & ((ttx << 4) + 15 <= whi);
        }
        if (__any_sync(FULL, off && inside)) continue;   // instant kill

        unsigned bmask = __ballot_sync(FULL, off && !inside);
        bool bad = false;
        while (bmask && !bad) {
            const int b = __ffs(bmask) - 1;
            bmask &= bmask - 1;
            const int by = b / 5;
            const int oty = tylo + by, otx = txlo + (b - by * 5);
            const int rlo = max(hlo, oty << 4), rhi = min(hhi, (oty << 4) + 15);
            const int clo = max(wlo, otx << 4), chi = min(whi, (otx << 4) + 15);
            const int ncm1 = chi - clo;                  // 0..15
            const int tot  = (rhi - rlo + 1) << 4;       // padded 16-wide rows, <=256
            // One parallel round: 8 predicated loads per lane, then a single ballot.
            float vmax = -1.0f;
            #pragma unroll
            for (int kk = 0; kk < 8; ++kk) {
                const int i = lane + (kk << 5);
                if (i < tot && (i & 15) <= ncm1) {
                    const int r = rlo + (i >> 4);
                    const int c = clo + (i & 15);
                    vmax = fmaxf(vmax, __ldg(&img[(r << IMG_SH) + c]));
                }
            }
            bad = __any_sync(FULL, vmax > pv);
        }
        if (!bad && lane == 0) {
            int s = atomicAdd(&g_peak_count, 1);
            if (s < PEAK_CAP) g_peaks[s] = lin;
        }
    }
}

// Warp per peak; peaks staged in SMEM (stride-32 LDS inner loop, conflict-free).
__global__ void rank_kernel(float* __restrict__ out) {
    __shared__ int sp[PEAK_CAP];
    const int cnt  = min(g_peak_count, PEAK_CAP);
    for (int j = threadIdx.x; j < cnt; j += blockDim.x) sp[j] = g_peaks[j];
    __syncthreads();

    const int lane = threadIdx.x & 31;
    const int gw   = (blockIdx.x * blockDim.x + threadIdx.x) >> 5;
    const int nw   = (gridDim.x * blockDim.x) >> 5;

    for (int i = gw; i < cnt; i += nw) {
        const int lin = sp[i];
        int r = 0;
        for (int j = lane; j < cnt; j += 32) r += (sp[j] < lin);
        #pragma unroll
        for (int off = 16; off; off >>= 1)
            r += __shfl_xor_sync(FULL, r, off);
        if (lane == 0 && r < MAXD) {
            const int rem = lin & ((1 << 20) - 1);
            reinterpret_cast<float4*>(out)[r] =
                make_float4((float)(lin >> 20), 0.0f,
                            (float)(rem >> IMG_SH), (float)(rem & 1023));
        }
    }
}

extern "C" void kernel_launch(void* const* d_in, const int* in_sizes, int n_in,
                              void* d_out, int out_size) {
    const float* x = (const float*)d_in[0];
    float* out = (float*)d_out;

    cand_kernel<<<1024, 256>>>(x, out);      // warp per 2x2 tile quad

    verify_kernel<<<NTILES / 8, 256>>>(x);

    rank_kernel<<<128, 256>>>(out);
}

// round 13
// speedup vs baseline: 2.1396x; 1.0621x over previous
#include <cuda_runtime.h>

// NMS peak detection, exact:
//   x: (8, 1, 1024, 1024) fp32
//   peak(p) <=> x[p] > 0.5 && no q in 51x51 window with x[q] > x[p]
//   output (float32): (4096, 4) rows [n, c, h, w] in row-major linear-index order, -1 fill.
//
// 16x16 aligned tile grid (64x64 tiles/image):
//   cand:   warp == horizontal TILE PAIR (32x16 px). 4 float4 loads/lane (full 128B
//           lines), 32 regs -> ~80% occ. Shuffle chain {16,8,2,1} (lane bit2 = tile)
//           reduces each 16-lane tile group. Emission: only lanes whose partial max
//           equals the tile max rescan their 16 regs. Fuses out fill + counter reset.
//   verify: warp == tile, <=25 covering tiles probed via fixed 5x5 map. Fully-inside
//           offender kills with zero element loads; boundary offenders get ONE parallel
//           8-load round per lane (single ballot). pv load hoisted before slot shuffle.
//   rank:   warp per peak; peaks staged in SMEM per block (stride-32 LDS inner loop).

#define IMG_SH 10          // 1024
#define NIMG   8
#define RAD    25
#define NT     64          // tiles per side
#define NTILES (NIMG * NT * NT)
#define MAXD   4096
#define PEAK_CAP 8192
#define FULL   0xffffffffu

__device__ int   g_cand[NTILES * 3];   // linear indices, -1 = empty
__device__ float g_tilemax[NTILES];
__device__ int   g_peak_count;
__device__ int   g_peaks[PEAK_CAP];

// 2048 blocks x 256 threads; 8 warps/block, warp == one horizontal tile pair.
__global__ void cand_kernel(const float* __restrict__ x, float* __restrict__ out) {
    const int tid  = threadIdx.x;
    const int lane = tid & 31;
    const int wid  = tid >> 5;

    // Fused init: -1 fill of 4096x4 output (blocks 0..15) + counter reset (block 16).
    if (blockIdx.x < 16)
        reinterpret_cast<float4*>(out)[(blockIdx.x << 8) + tid] =
            make_float4(-1.0f, -1.0f, -1.0f, -1.0f);
    if (blockIdx.x == 16 && tid == 0) g_peak_count = 0;

    const int tp    = (blockIdx.x << 3) + wid;   // tile-pair id, 0..16383
    const int tileA = tp << 1;
    const int n     = tileA >> 12;
    const int ty    = (tileA >> 6) & 63;
    const int txA   = tileA & 63;                // even
    const int row0  = lane >> 3;                 // 0..3
    const int colp  = (lane & 7) << 2;           // 0..28 within 32-wide pair

    const float* base = x + ((size_t)n << 20)
                          + (((ty << 4) + row0) << IMG_SH)
                          + (txA << 4) + colp;

    const float4 f0 = *reinterpret_cast<const float4*>(base);
    const float4 f1 = *reinterpret_cast<const float4*>(base + (4 << IMG_SH));
    const float4 f2 = *reinterpret_cast<const float4*>(base + (8 << IMG_SH));
    const float4 f3 = *reinterpret_cast<const float4*>(base + (12 << IMG_SH));

    // Per-lane partial max over 16 elems.
    const float p = fmaxf(fmaxf(fmaxf(fmaxf(f0.x, f0.y), fmaxf(f0.z, f0.w)),
                                fmaxf(fmaxf(f1.x, f1.y), fmaxf(f1.z, f1.w))),
                          fmaxf(fmaxf(fmaxf(f2.x, f2.y), fmaxf(f2.z, f2.w)),
                                fmaxf(fmaxf(f3.x, f3.y), fmaxf(f3.z, f3.w))));

    // Reduce over the 16 lanes sharing bit2 (= same tile): offsets keep bit2 fixed.
    float m = p;
    m = fmaxf(m, __shfl_xor_sync(FULL, m, 16));
    m = fmaxf(m, __shfl_xor_sync(FULL, m, 8));
    m = fmaxf(m, __shfl_xor_sync(FULL, m, 2));
    m = fmaxf(m, __shfl_xor_sync(FULL, m, 1));

    const int myTile = tileA + ((lane >> 2) & 1);
    if (lane == 0 || lane == 4) g_tilemax[myTile] = m;
    if (lane < 3)               g_cand[tileA * 3 + lane] = -1;
    if (lane >= 4 && lane < 7)  g_cand[(tileA + 1) * 3 + (lane - 4)] = -1;

    __shared__ int scnt[16];
    if (lane == 0 || lane == 4) scnt[(wid << 1) | (lane >> 2)] = 0;
    __syncwarp();

    if (m <= 0.5f) return;

    // Only lanes holding the tile max rescan their 16 registers (1-2 lanes/warp).
    if (p == m) {
        const int sidx = (wid << 1) | ((lane >> 2) & 1);
        const int lin0 = (n << 20) + (((ty << 4) + row0) << IMG_SH) + (txA << 4) + colp;
        const float v[16] = {f0.x, f0.y, f0.z, f0.w, f1.x, f1.y, f1.z, f1.w,
                             f2.x, f2.y, f2.z, f2.w, f3.x, f3.y, f3.z, f3.w};
        #pragma unroll
        for (int k = 0; k < 16; ++k) {
            if (v[k] == m) {
                int s = atomicAdd(&scnt[sidx], 1);
                if (s < 3)
                    g_cand[myTile * 3 + s] = lin0 + ((k >> 2) << (IMG_SH + 2)) + (k & 3);
            }
        }
    }
}

// One warp per tile. Tilemax pruning; boundary offenders: one parallel 8-load round.
__global__ void verify_kernel(const float* __restrict__ x) {
    const int lane = threadIdx.x & 31;
    const int tile = (blockIdx.x << 3) + (threadIdx.x >> 5);

    // Issue both independent loads up front (pv does not depend on the slots).
    const float pv = __ldg(&g_tilemax[tile]);
    int slot = (lane < 3) ? __ldg(&g_cand[tile * 3 + lane]) : -1;
    const int c0 = __shfl_sync(FULL, slot, 0);
    if (c0 < 0) return;                      // tile max <= 0.5
    const int c1 = __shfl_sync(FULL, slot, 1);
    const int c2 = __shfl_sync(FULL, slot, 2);
    const int n = tile >> 12;
    const float* img = x + ((size_t)n << 20);
    const float* tm  = g_tilemax + (n << 12);

    #pragma unroll
    for (int k = 0; k < 3; ++k) {
        const int lin = (k == 0) ? c0 : (k == 1) ? c1 : c2;
        if (lin < 0) break;
        const int rem = lin & ((1 << 20) - 1);
        const int h = rem >> IMG_SH;
        const int w = rem & 1023;

        const int hlo = max(h - RAD, 0), hhi = min(h + RAD, 1023);
        const int wlo = max(w - RAD, 0), whi = min(w + RAD, 1023);
        const int tylo = hlo >> 4, tyhi = hhi >> 4;
        const int txlo = wlo >> 4, txhi = whi >> 4;

        // Fixed 5x5 probe grid; constant divisor -> mul/shift. Guarded by range.
        const int dy = lane / 5, dx = lane - dy * 5;
        const int tty = tylo + dy, ttx = txlo + dx;
        bool off = false, inside = false;
        if (lane < 25 && tty <= tyhi && ttx <= txhi) {
            off = __ldg(&tm[(tty << 6) + ttx]) > pv;
            inside = ((tty << 4) >= hlo) & ((tty << 4) + 15 <= hhi) &
                     ((ttx << 4) >= wlo) & ((ttx << 4) + 15 <= whi);
        }
        if (__any_sync(FULL, off && inside)) continue;   // instant kill

        unsigned bmask = __ballot_sync(FULL, off && !inside);
        bool bad = false;
        while (bmask && !bad) {
            const int b = __ffs(bmask) - 1;
            bmask &= bmask - 1;
            const int by = b / 5;
            const int oty = tylo + by, otx = txlo + (b - by * 5);
            const int rlo = max(hlo, oty << 4), rhi = min(hhi, (oty << 4) + 15);
            const int clo = max(wlo, otx << 4), chi = min(whi, (otx << 4) + 15);
            const int ncm1 = chi - clo;                  // 0..15
            const int tot  = (rhi - rlo + 1) << 4;       // padded 16-wide rows, <=256
            // One parallel round: 8 predicated loads per lane, then a single ballot.
            float vmax = -1.0f;
            #pragma unroll
            for (int kk = 0; kk < 8; ++kk) {
                const int i = lane + (kk << 5);
                if (i < tot && (i & 15) <= ncm1) {
                    const int r = rlo + (i >> 4);
                    const int c = clo + (i & 15);
                    vmax = fmaxf(vmax, __ldg(&img[(r << IMG_SH) + c]));
                }
            }
            bad = __any_sync(FULL, vmax > pv);
        }
        if (!bad && lane == 0) {
            int s = atomicAdd(&g_peak_count, 1);
            if (s < PEAK_CAP) g_peaks[s] = lin;
        }
    }
}

// Warp per peak; peaks staged in SMEM (stride-32 LDS inner loop, conflict-free).
__global__ void rank_kernel(float* __restrict__ out) {
    __shared__ int sp[PEAK_CAP];
    const int cnt  = min(g_peak_count, PEAK_CAP);
    for (int j = threadIdx.x; j < cnt; j += blockDim.x) sp[j] = g_peaks[j];
    __syncthreads();

    const int lane = threadIdx.x & 31;
    const int gw   = (blockIdx.x * blockDim.x + threadIdx.x) >> 5;
    const int nw   = (gridDim.x * blockDim.x) >> 5;

    for (int i = gw; i < cnt; i += nw) {
        const int lin = sp[i];
        int r = 0;
        for (int j = lane; j < cnt; j += 32) r += (sp[j] < lin);
        #pragma unroll
        for (int off = 16; off; off >>= 1)
            r += __shfl_xor_sync(FULL, r, off);
        if (lane == 0 && r < MAXD) {
            const int rem = lin & ((1 << 20) - 1);
            reinterpret_cast<float4*>(out)[r] =
                make_float4((float)(lin >> 20), 0.0f,
                            (float)(rem >> IMG_SH), (float)(rem & 1023));
        }
    }
}

extern "C" void kernel_launch(void* const* d_in, const int* in_sizes, int n_in,
                              void* d_out, int out_size) {
    const float* x = (const float*)d_in[0];
    float* out = (float*)d_out;

    cand_kernel<<<2048, 256>>>(x, out);      // warp per horizontal tile pair

    verify_kernel<<<NTILES / 8, 256>>>(x);

    rank_kernel<<<128, 256>>>(out);
}

// round 15
// speedup vs baseline: 2.1422x; 1.0012x over previous
#include <cuda_runtime.h>

// NMS peak detection, exact — SINGLE persistent kernel with software grid barriers.
//   x: (8, 1, 1024, 1024) fp32
//   peak(p) <=> x[p] > 0.5 && no q in 51x51 window with x[q] > x[p]
//   output (float32): (4096, 4) rows [n, c, h, w] in row-major linear-index order, -1 fill.
//
// Phase 1 (cand):  warp == horizontal 16x16-tile pair (32x16 px), 4 pairs/warp.
//                  4 float4 loads/lane (full 128B lines); shuffle chain {16,8,2,1}
//                  (lane bit2 = tile) reduces each 16-lane tile group. Only lanes whose
//                  partial max equals the tile max rescan their 16 regs for emission.
// Phase 2 (verify):warp == tile, 8 tiles/warp. <=25 covering tiles probed via fixed
//                  5x5 map; fully-inside offender kills with zero element loads;
//                  boundary offenders get one parallel 8-load round (single ballot).
// Phase 3 (rank):  peaks staged to SMEM; warp per peak, O(n^2/32) -> nonzero() order.
//
// Grid barriers: sense-reversing epoch barrier. 512 blocks, __launch_bounds__(256,4)
// guarantees >=592 resident blocks -> no deadlock. Barrier count returns to 0 and the
// epoch only grows, so state is consistent across graph replays.

#define IMG_SH 10          // 1024
#define NIMG   8
#define RAD    25
#define NT     64          // tiles per side
#define NTILES (NIMG * NT * NT)      // 32768
#define MAXD   4096
#define PEAK_CAP 8192
#define FULL   0xffffffffu
#define NBLK   512
#define NWARPS (NBLK * 8)            // 4096

__device__ int   g_cand[NTILES * 3];   // linear indices, -1 = empty
__device__ float g_tilemax[NTILES];
__device__ int   g_peak_count;
__device__ int   g_peaks[PEAK_CAP];
__device__ int   g_bar_count;          // zero-init; returns to zero after each barrier
__device__ int   g_bar_epoch;          // monotonically increasing

__device__ __forceinline__ void grid_barrier() {
    __syncthreads();
    if (threadIdx.x == 0) {
        __threadfence();
        const int old = atomicAdd(&g_bar_epoch, 0);   // read BEFORE arriving: safe
        if (atomicAdd(&g_bar_count, 1) == NBLK - 1) {
            atomicExch(&g_bar_count, 0);              // reset happens-before epoch bump
            __threadfence();
            atomicAdd(&g_bar_epoch, 1);
        } else {
            while (atomicAdd(&g_bar_epoch, 0) == old) { __nanosleep(64); }
        }
    }
    __syncthreads();
}

__global__ __launch_bounds__(256, 4)
void nms_kernel(const float* __restrict__ x, float* __restrict__ out) {
    __shared__ int scnt[16];
    __shared__ int sp[PEAK_CAP];

    const int tid  = threadIdx.x;
    const int lane = tid & 31;
    const int wid  = tid >> 5;
    const int bwarp = (blockIdx.x << 3) + wid;   // 0..4095

    // ── Phase 0 (fused into phase 1): output -1 fill + peak counter reset ──
    if (blockIdx.x < 16)
        reinterpret_cast<float4*>(out)[(blockIdx.x << 8) + tid] =
            make_float4(-1.0f, -1.0f, -1.0f, -1.0f);
    if (blockIdx.x == 16 && tid == 0) g_peak_count = 0;

    // ── Phase 1: candidates ── 4 tile pairs per warp.
    #pragma unroll
    for (int it = 0; it < 4; ++it) {
        const int tp    = it * NWARPS + bwarp;       // 0..16383
        const int tileA = tp << 1;
        const int n     = tileA >> 12;
        const int ty    = (tileA >> 6) & 63;
        const int txA   = tileA & 63;                // even
        const int row0  = lane >> 3;                 // 0..3
        const int colp  = (lane & 7) << 2;           // 0..28 within 32-wide pair

        const float* base = x + ((size_t)n << 20)
                              + (((ty << 4) + row0) << IMG_SH)
                              + (txA << 4) + colp;

        const float4 f0 = *reinterpret_cast<const float4*>(base);
        const float4 f1 = *reinterpret_cast<const float4*>(base + (4 << IMG_SH));
        const float4 f2 = *reinterpret_cast<const float4*>(base + (8 << IMG_SH));
        const float4 f3 = *reinterpret_cast<const float4*>(base + (12 << IMG_SH));

        const float p = fmaxf(fmaxf(fmaxf(fmaxf(f0.x, f0.y), fmaxf(f0.z, f0.w)),
                                    fmaxf(fmaxf(f1.x, f1.y), fmaxf(f1.z, f1.w))),
                              fmaxf(fmaxf(fmaxf(f2.x, f2.y), fmaxf(f2.z, f2.w)),
                                    fmaxf(fmaxf(f3.x, f3.y), fmaxf(f3.z, f3.w))));

        float m = p;
        m = fmaxf(m, __shfl_xor_sync(FULL, m, 16));
        m = fmaxf(m, __shfl_xor_sync(FULL, m, 8));
        m = fmaxf(m, __shfl_xor_sync(FULL, m, 2));
        m = fmaxf(m, __shfl_xor_sync(FULL, m, 1));

        const int myTile = tileA + ((lane >> 2) & 1);
        if (lane == 0 || lane == 4) g_tilemax[myTile] = m;
        if (lane < 3)               g_cand[tileA * 3 + lane] = -1;
        if (lane >= 4 && lane < 7)  g_cand[(tileA + 1) * 3 + (lane - 4)] = -1;

        if (lane == 0 || lane == 4) scnt[(wid << 1) | (lane >> 2)] = 0;
        __syncwarp();

        if (m > 0.5f && p == m) {
            const int sidx = (wid << 1) | ((lane >> 2) & 1);
            const int lin0 = (n << 20) + (((ty << 4) + row0) << IMG_SH) + (txA << 4) + colp;
            const float v[16] = {f0.x, f0.y, f0.z, f0.w, f1.x, f1.y, f1.z, f1.w,
                                 f2.x, f2.y, f2.z, f2.w, f3.x, f3.y, f3.z, f3.w};
            #pragma unroll
            for (int k = 0; k < 16; ++k) {
                if (v[k] == m) {
                    int s = atomicAdd(&scnt[sidx], 1);
                    if (s < 3)
                        g_cand[myTile * 3 + s] = lin0 + ((k >> 2) << (IMG_SH + 2)) + (k & 3);
                }
            }
        }
        __syncwarp();
    }

    grid_barrier();

    // ── Phase 2: verify ── 8 tiles per warp.
    for (int it = 0; it < 8; ++it) {
        const int tile = it * NWARPS + bwarp;        // 0..32767

        const float pv = __ldg(&g_tilemax[tile]);
        int slot = (lane < 3) ? __ldg(&g_cand[tile * 3 + lane]) : -1;
        const int c0 = __shfl_sync(FULL, slot, 0);
        if (c0 < 0) continue;                        // tile max <= 0.5
        const int c1 = __shfl_sync(FULL, slot, 1);
        const int c2 = __shfl_sync(FULL, slot, 2);
        const int n = tile >> 12;
        const float* img = x + ((size_t)n << 20);
        const float* tm  = g_tilemax + (n << 12);

        #pragma unroll
        for (int k = 0; k < 3; ++k) {
            const int lin = (k == 0) ? c0 : (k == 1) ? c1 : c2;
            if (lin < 0) break;
            const int rem = lin & ((1 << 20) - 1);
            const int h = rem >> IMG_SH;
            const int w = rem & 1023;

            const int hlo = max(h - RAD, 0), hhi = min(h + RAD, 1023);
            const int wlo = max(w - RAD, 0), whi = min(w + RAD, 1023);
            const int tylo = hlo >> 4, tyhi = hhi >> 4;
            const int txlo = wlo >> 4, txhi = whi >> 4;

            const int dy = lane / 5, dx = lane - dy * 5;   // const div
            const int tty = tylo + dy, ttx = txlo + dx;
            bool off = false, inside = false;
            if (lane < 25 && tty <= tyhi && ttx <= txhi) {
                off = __ldg(&tm[(tty << 6) + ttx]) > pv;
                inside = ((tty << 4) >= hlo) & ((tty << 4) + 15 <= hhi) &
                         ((ttx << 4) >= wlo) & ((ttx << 4) + 15 <= whi);
            }
            if (__any_sync(FULL, off && inside)) continue;   // instant kill

            unsigned bmask = __ballot_sync(FULL, off && !inside);
            bool bad = false;
            while (bmask && !bad) {
                const int b = __ffs(bmask) - 1;
                bmask &= bmask - 1;
                const int by = b / 5;
                const int oty = tylo + by, otx = txlo + (b - by * 5);
                const int rlo = max(hlo, oty << 4), rhi = min(hhi, (oty << 4) + 15);
                const int clo = max(wlo, otx << 4), chi = min(whi, (otx << 4) + 15);
                const int ncm1 = chi - clo;                  // 0..15
                const int tot  = (rhi - rlo + 1) << 4;       // padded 16-wide rows
                float vmax = -1.0f;
                #pragma unroll
                for (int kk = 0; kk < 8; ++kk) {
                    const int i = lane + (kk << 5);
                    if (i < tot && (i & 15) <= ncm1) {
                        const int r = rlo + (i >> 4);
                        const int c = clo + (i & 15);
                        vmax = fmaxf(vmax, __ldg(&img[(r << IMG_SH) + c]));
                    }
                }
                bad = __any_sync(FULL, vmax > pv);
            }
            if (!bad && lane == 0) {
                int s = atomicAdd(&g_peak_count, 1);
                if (s < PEAK_CAP) g_peaks[s] = lin;
            }
        }
    }

    grid_barrier();

    // ── Phase 3: rank ── peaks staged to SMEM, warp per peak.
    const int cnt = min(g_peak_count, PEAK_CAP);
    for (int j = tid; j < cnt; j += 256) sp[j] = g_peaks[j];
    __syncthreads();

    for (int i = bwarp; i < cnt; i += NWARPS) {
        const int lin = sp[i];
        int r = 0;
        for (int j = lane; j < cnt; j += 32) r += (sp[j] < lin);
        #pragma unroll
        for (int off = 16; off; off >>= 1)
            r += __shfl_xor_sync(FULL, r, off);
        if (lane == 0 && r < MAXD) {
            const int rem = lin & ((1 << 20) - 1);
            reinterpret_cast<float4*>(out)[r] =
                make_float4((float)(lin >> 20), 0.0f,
                            (float)(rem >> IMG_SH), (float)(rem & 1023));
        }
    }
}

extern "C" void kernel_launch(void* const* d_in, const int* in_sizes, int n_in,
                              void* d_out, int out_size) {
    const float* x = (const float*)d_in[0];
    float* out = (float*)d_out;

    nms_kernel<<<NBLK, 256>>>(x, out);
}